// round 1
// baseline (speedup 1.0000x reference)
#include <cuda_runtime.h>
#include <math.h>

#define BB  2
#define TT  8192
#define EE  256
#define CSZ 128
#define NCH 64      // TT / CSZ
#define KT  8       // K slots (7 retrieved + current)

// ---- scratch (device globals; no allocation allowed) ----
__device__ float g_cn[(size_t)BB * TT * EE];        // normalized rows, 16 MB
__device__ float g_scores[BB * NCH * NCH];
__device__ int   g_src[BB * NCH * KT];
__device__ float g_wgt[BB * NCH * KT];

// ============================================================
// 1) Row normalization: cn[r] = x[r] / (||x[r]|| + 1e-6)
//    one warp per row of 256 floats
// ============================================================
__global__ void normalize_k(const float* __restrict__ x) {
    int row  = blockIdx.x * 8 + (threadIdx.x >> 5);
    int lane = threadIdx.x & 31;
    const float4* xr = (const float4*)(x + (size_t)row * EE);
    float4 v0 = xr[lane];
    float4 v1 = xr[lane + 32];
    float ss = v0.x*v0.x + v0.y*v0.y + v0.z*v0.z + v0.w*v0.w
             + v1.x*v1.x + v1.y*v1.y + v1.z*v1.z + v1.w*v1.w;
    #pragma unroll
    for (int o = 16; o > 0; o >>= 1) ss += __shfl_xor_sync(0xffffffffu, ss, o);
    float inv = 1.0f / (sqrtf(ss) + 1e-6f);
    v0.x *= inv; v0.y *= inv; v0.z *= inv; v0.w *= inv;
    v1.x *= inv; v1.y *= inv; v1.z *= inv; v1.w *= inv;
    float4* cr = (float4*)(g_cn + (size_t)row * EE);
    cr[lane]      = v0;
    cr[lane + 32] = v1;
}

// ============================================================
// 2) Score kernel: one CTA per (b,i,j), j<i.
//    C = cn_i @ cn_j^T (128x128x256), score = sum_c max_d C[c,d]
//    256 threads, 8x8 register tile, transposed smem tiles.
// ============================================================
__global__ void score_k() {
    int j = blockIdx.x, i = blockIdx.y, b = blockIdx.z;
    if (j >= i) return;

    __shared__ float As[16][132];
    __shared__ float Bs[16][132];
    __shared__ float wsum[4];

    const float* A = g_cn + (((size_t)b * NCH + i) * CSZ) * EE;
    const float* Bp = g_cn + (((size_t)b * NCH + j) * CSZ) * EE;

    int tid = threadIdx.x;
    int tx = tid & 15, ty = tid >> 4;

    float acc[8][8];
    #pragma unroll
    for (int u = 0; u < 8; u++)
        #pragma unroll
        for (int v = 0; v < 8; v++) acc[u][v] = 0.0f;

    for (int k0 = 0; k0 < EE; k0 += 16) {
        #pragma unroll
        for (int it = 0; it < 2; it++) {
            int f   = tid + it * 256;       // 0..511
            int row = f >> 2;               // 0..127
            int kq  = (f & 3) * 4;          // 0,4,8,12
            float4 va = *(const float4*)(A  + (size_t)row * EE + k0 + kq);
            As[kq+0][row] = va.x; As[kq+1][row] = va.y;
            As[kq+2][row] = va.z; As[kq+3][row] = va.w;
            float4 vb = *(const float4*)(Bp + (size_t)row * EE + k0 + kq);
            Bs[kq+0][row] = vb.x; Bs[kq+1][row] = vb.y;
            Bs[kq+2][row] = vb.z; Bs[kq+3][row] = vb.w;
        }
        __syncthreads();
        #pragma unroll
        for (int k = 0; k < 16; k++) {
            float a[8], bb[8];
            *(float4*)&a[0]  = *(const float4*)&As[k][ty * 8];
            *(float4*)&a[4]  = *(const float4*)&As[k][ty * 8 + 4];
            *(float4*)&bb[0] = *(const float4*)&Bs[k][tx * 8];
            *(float4*)&bb[4] = *(const float4*)&Bs[k][tx * 8 + 4];
            #pragma unroll
            for (int u = 0; u < 8; u++)
                #pragma unroll
                for (int v = 0; v < 8; v++)
                    acc[u][v] = fmaf(a[u], bb[v], acc[u][v]);
        }
        __syncthreads();
    }

    // per-thread row max over its 8 columns -> red[row][tx]
    float* red = &As[0][0];   // reuse, 128*16 floats fit in As
    #pragma unroll
    for (int u = 0; u < 8; u++) {
        float m = acc[u][0];
        #pragma unroll
        for (int v = 1; v < 8; v++) m = fmaxf(m, acc[u][v]);
        red[(ty * 8 + u) * 16 + tx] = m;
    }
    __syncthreads();

    float total = 0.0f;
    if (tid < 128) {
        const float* rr = red + tid * 16;
        float m = rr[0];
        #pragma unroll
        for (int t = 1; t < 16; t++) m = fmaxf(m, rr[t]);
        total = m;   // max over d for row c=tid
    }
    #pragma unroll
    for (int o = 16; o > 0; o >>= 1) total += __shfl_xor_sync(0xffffffffu, total, o);
    if (tid < 128 && (tid & 31) == 0) wsum[tid >> 5] = total;
    __syncthreads();
    if (tid == 0)
        g_scores[(b * NCH + i) * NCH + j] = wsum[0] + wsum[1] + wsum[2] + wsum[3];
}

// ============================================================
// 3) Top-(K-1) selection + weights per (b,i). Serial, tiny.
//    Stable descending (lowest index wins ties) matches lax.top_k.
// ============================================================
__global__ void topk_k() {
    if (threadIdx.x != 0) return;
    int i = blockIdx.x, b = blockIdx.y;
    const float* srow = g_scores + (b * NCH + i) * NCH;

    int num_sel = i < 7 ? i : 7;
    int shift   = 7 - num_sel;

    int   idxs[7];
    float vals[7];
    bool  used[NCH];
    for (int t = 0; t < NCH; t++) used[t] = false;

    for (int r = 0; r < num_sel; r++) {
        float best = -3.0e38f; int bi = 0;
        for (int jj = 0; jj < i; jj++) {
            if (used[jj]) continue;
            float v = srow[jj];
            if (v > best) { best = v; bi = jj; }
        }
        used[bi] = true; idxs[r] = bi; vals[r] = best;
    }

    float vmin = (num_sel > 0) ? vals[num_sel - 1] : 0.0f;
    int base = (b * NCH + i) * KT;
    for (int slot = 0; slot < 7; slot++) {
        if (slot >= shift) {
            int r = slot - shift;
            g_src[base + slot] = idxs[r];
            g_wgt[base + slot] = vals[r] / (vmin + 1e-6f);
        } else {
            g_src[base + slot] = i;     // dummy, weight 0
            g_wgt[base + slot] = 0.0f;
        }
    }
    g_src[base + 7] = i;
    g_wgt[base + 7] = 1.0f;
}

// ============================================================
// 4) Output: per (b,i,half): out[128, 128] =
//    sum_slots w_s * dp[:, slot*128:+128] @ x[b, src_s] + x_chunk
// ============================================================
__global__ void out_k(const float* __restrict__ x, const float* __restrict__ dp,
                      float* __restrict__ out) {
    int half = blockIdx.x, i = blockIdx.y, b = blockIdx.z;
    int e0 = half * 128;

    __shared__ float As[16][132];
    __shared__ float Bs[16][132];
    __shared__ int   s_src[KT];
    __shared__ float s_w[KT];

    int tid = threadIdx.x;
    int tx = tid & 15, ty = tid >> 4;

    if (tid < KT) {
        s_src[tid] = g_src[(b * NCH + i) * KT + tid];
        s_w[tid]   = g_wgt[(b * NCH + i) * KT + tid];
    }
    __syncthreads();

    float acc[8][8];
    #pragma unroll
    for (int u = 0; u < 8; u++)
        #pragma unroll
        for (int v = 0; v < 8; v++) acc[u][v] = 0.0f;

    for (int s = 0; s < KT; s++) {
        float w = s_w[s];
        if (w == 0.0f) continue;   // uniform across block (shared)
        const float* Bsrc = x + (((size_t)b * TT + (size_t)s_src[s] * CSZ) * EE) + e0;

        for (int k0 = 0; k0 < CSZ; k0 += 16) {
            // A tile: dp[c][s*128 + k0 + k] transposed -> As[k][c]
            #pragma unroll
            for (int it = 0; it < 2; it++) {
                int f   = tid + it * 256;
                int row = f >> 2;
                int kq  = (f & 3) * 4;
                float4 va = *(const float4*)(dp + (size_t)row * 1024 + s * 128 + k0 + kq);
                As[kq+0][row] = va.x; As[kq+1][row] = va.y;
                As[kq+2][row] = va.z; As[kq+3][row] = va.w;
            }
            // B tile: Bs[k][e'] = w * x[b, src*128 + k0+k][e0+e']
            #pragma unroll
            for (int it = 0; it < 2; it++) {
                int f  = tid + it * 256;      // 0..511
                int r  = f >> 5;              // 0..15
                int c4 = (f & 31) * 4;        // 0..124
                float4 vb = *(const float4*)(Bsrc + (size_t)(k0 + r) * EE + c4);
                *(float4*)&Bs[r][c4] = make_float4(w*vb.x, w*vb.y, w*vb.z, w*vb.w);
            }
            __syncthreads();
            #pragma unroll
            for (int k = 0; k < 16; k++) {
                float a[8], bb[8];
                *(float4*)&a[0]  = *(const float4*)&As[k][ty * 8];
                *(float4*)&a[4]  = *(const float4*)&As[k][ty * 8 + 4];
                *(float4*)&bb[0] = *(const float4*)&Bs[k][tx * 8];
                *(float4*)&bb[4] = *(const float4*)&Bs[k][tx * 8 + 4];
                #pragma unroll
                for (int u = 0; u < 8; u++)
                    #pragma unroll
                    for (int v = 0; v < 8; v++)
                        acc[u][v] = fmaf(a[u], bb[v], acc[u][v]);
            }
            __syncthreads();
        }
    }

    // epilogue: += residual chunk, write out
    size_t obase = ((size_t)b * TT + (size_t)i * CSZ) * EE + e0;
    #pragma unroll
    for (int u = 0; u < 8; u++) {
        int row = ty * 8 + u;
        int col = tx * 8;
        const float4* xc = (const float4*)(x   + obase + (size_t)row * EE + col);
        float4*       oc = (float4*)      (out + obase + (size_t)row * EE + col);
        float4 x0 = xc[0], x1 = xc[1];
        oc[0] = make_float4(acc[u][0] + x0.x, acc[u][1] + x0.y,
                            acc[u][2] + x0.z, acc[u][3] + x0.w);
        oc[1] = make_float4(acc[u][4] + x1.x, acc[u][5] + x1.y,
                            acc[u][6] + x1.z, acc[u][7] + x1.w);
    }
}

// ============================================================
extern "C" void kernel_launch(void* const* d_in, const int* in_sizes, int n_in,
                              void* d_out, int out_size) {
    const float* x  = (const float*)d_in[0];   // [B, T, E] fp32
    const float* dp = (const float*)d_in[1];   // [CS, L] fp32
    float* out = (float*)d_out;

    normalize_k<<<(BB * TT) / 8, 256>>>(x);
    score_k<<<dim3(NCH, NCH, BB), 256>>>();
    topk_k<<<dim3(NCH, BB), 32>>>();
    out_k<<<dim3(2, NCH, BB), 256>>>(x, dp, out);
}

// round 6
// speedup vs baseline: 2.0023x; 2.0023x over previous
#include <cuda_runtime.h>
#include <cuda_bf16.h>
#include <math.h>
#include <stdint.h>

#define BB  2
#define TT  8192
#define EE  256
#define CSZ 128
#define NCH 64      // TT / CSZ
#define KT  8       // K slots (7 retrieved + current)

// ---- scratch (device globals; no allocation allowed) ----
__device__ __nv_bfloat16 g_hi[(size_t)BB * TT * EE];   // bf16 hi of normalized rows
__device__ __nv_bfloat16 g_lo[(size_t)BB * TT * EE];   // bf16 residual
__device__ float g_scores[BB * NCH * NCH];
__device__ int   g_src[BB * NCH * KT];
__device__ float g_wgt[BB * NCH * KT];

// ================= helpers =================
__device__ __forceinline__ uint32_t smem_u32(const void* p) {
    uint32_t a;
    asm("{ .reg .u64 t; cvta.to.shared.u64 t, %1; cvt.u32.u64 %0, t; }" : "=r"(a) : "l"(p));
    return a;
}
#define LDSM_X4(R, a) \
    asm volatile("ldmatrix.sync.aligned.m8n8.x4.shared.b16 {%0,%1,%2,%3}, [%4];" \
        : "=r"((R)[0]), "=r"((R)[1]), "=r"((R)[2]), "=r"((R)[3]) : "r"(a))
#define MMA16816(D, A, B0, B1) \
    asm volatile("mma.sync.aligned.m16n8k16.row.col.f32.bf16.bf16.f32 " \
        "{%0,%1,%2,%3}, {%4,%5,%6,%7}, {%8,%9}, {%0,%1,%2,%3};" \
        : "+f"((D)[0]), "+f"((D)[1]), "+f"((D)[2]), "+f"((D)[3]) \
        : "r"((A)[0]), "r"((A)[1]), "r"((A)[2]), "r"((A)[3]), "r"(B0), "r"(B1))

// ============================================================
// 1) Row normalization -> bf16 hi/lo split of cn
// ============================================================
__global__ void normalize_k(const float* __restrict__ x) {
    int row  = blockIdx.x * 8 + (threadIdx.x >> 5);
    int lane = threadIdx.x & 31;
    const float4* xr = (const float4*)(x + (size_t)row * EE);
    float4 v0 = xr[lane];
    float4 v1 = xr[lane + 32];
    float ss = v0.x*v0.x + v0.y*v0.y + v0.z*v0.z + v0.w*v0.w
             + v1.x*v1.x + v1.y*v1.y + v1.z*v1.z + v1.w*v1.w;
    #pragma unroll
    for (int o = 16; o > 0; o >>= 1) ss += __shfl_xor_sync(0xffffffffu, ss, o);
    float inv = 1.0f / (sqrtf(ss) + 1e-6f);

    float f[8] = { v0.x*inv, v0.y*inv, v0.z*inv, v0.w*inv,
                   v1.x*inv, v1.y*inv, v1.z*inv, v1.w*inv };
    __nv_bfloat16 h[8], l[8];
    #pragma unroll
    for (int t = 0; t < 8; t++) {
        h[t] = __float2bfloat16(f[t]);
        l[t] = __float2bfloat16(f[t] - __bfloat162float(h[t]));
    }
    size_t base = (size_t)row * EE;
    uint32_t* hp = (uint32_t*)(g_hi + base);
    uint32_t* lp = (uint32_t*)(g_lo + base);
    #pragma unroll
    for (int t = 0; t < 2; t++) {
        // f[4t..4t+3] are bf16 elements (t*128 + 4*lane ..+3) -> uint32 index t*64 + 2*lane
        int eb = t * 64 + lane * 2;
        __nv_bfloat162 hh0(h[t*4+0], h[t*4+1]), hh1(h[t*4+2], h[t*4+3]);
        __nv_bfloat162 ll0(l[t*4+0], l[t*4+1]), ll1(l[t*4+2], l[t*4+3]);
        hp[eb]     = *(uint32_t*)&hh0;
        hp[eb + 1] = *(uint32_t*)&hh1;
        lp[eb]     = *(uint32_t*)&ll0;
        lp[eb + 1] = *(uint32_t*)&ll1;
    }
}

// ============================================================
// 2) Score kernel via mma.sync bf16x3. One CTA (8 warps) per (b,i,j), j<i.
//    D = Ah·Bh^T + Ah·Bl^T + Al·Bh^T  (128x128, K=256 in 4 chunks of 64)
//    score = sum_c max_d D[c][d]
// Tiles: 128 rows x 64 bf16 (128B rows), XOR-8 swizzle on 16B granules.
// ============================================================
__global__ void __launch_bounds__(256, 2)
score_hmma_k() {
    int j = blockIdx.x, i = blockIdx.y, b = blockIdx.z;
    if (j >= i) return;

    extern __shared__ char smem[];
    uint32_t sb = smem_u32(smem);
    const uint32_t TSZ = 16384;
    // tiles: 0=Ah, 1=Al, 2=Bh, 3=Bl ; red buffer after 64KB
    float* red  = (float*)(smem + 4 * TSZ);          // [128][2]
    float* wsum = (float*)(smem + 4 * TSZ + 1024);   // [8]

    int tid  = threadIdx.x;
    int wid  = tid >> 5;
    int lane = tid & 31;
    int wr = wid >> 1;           // 0..3 : rows [wr*32, +32)
    int wc = wid & 1;            // 0..1 : cols [wc*64, +64)

    const __nv_bfloat16* srcp[4] = {
        g_hi + ((size_t)(b * NCH + i) * CSZ) * EE,
        g_lo + ((size_t)(b * NCH + i) * CSZ) * EE,
        g_hi + ((size_t)(b * NCH + j) * CSZ) * EE,
        g_lo + ((size_t)(b * NCH + j) * CSZ) * EE
    };

    float acc[2][8][4];
    #pragma unroll
    for (int mt = 0; mt < 2; mt++)
        #pragma unroll
        for (int nt = 0; nt < 8; nt++)
            #pragma unroll
            for (int e = 0; e < 4; e++) acc[mt][nt][e] = 0.0f;

    // precompute ldmatrix lane address components
    int a_r   = (lane & 15);          // row within m16
    int a_c   = (lane >> 4);          // k half (0/1)
    int b_r   = (lane & 7) + ((lane >> 4) << 3);   // n row within n16
    int b_c   = (lane >> 3) & 1;                    // k half

    for (int c = 0; c < 4; c++) {
        int k0 = c * 64;
        // ---- load 4 tiles [128 x 64 bf16], XOR-swizzled ----
        #pragma unroll
        for (int t = 0; t < 4; t++) {
            const __nv_bfloat16* s = srcp[t] + k0;
            char* tb = smem + t * TSZ;
            #pragma unroll
            for (int q = 0; q < 4; q++) {
                int idx = q * 256 + tid;       // 0..1023
                int r   = idx >> 3;            // 0..127
                int c8  = idx & 7;             // 16B granule
                uint4 v = *(const uint4*)(s + (size_t)r * EE + c8 * 8);
                *(uint4*)(tb + r * 128 + ((c8 ^ (r & 7)) << 4)) = v;
            }
        }
        __syncthreads();

        #pragma unroll
        for (int kk = 0; kk < 4; kk++) {
            // A fragments (hi & lo) for 2 m16 tiles
            uint32_t ahi[2][4], alo[2][4];
            #pragma unroll
            for (int mt = 0; mt < 2; mt++) {
                int r   = wr * 32 + mt * 16 + a_r;
                int c16 = kk * 2 + a_c;
                uint32_t off = (uint32_t)(r * 128 + ((c16 ^ (r & 7)) << 4));
                LDSM_X4(ahi[mt], sb + 0 * TSZ + off);
                LDSM_X4(alo[mt], sb + 1 * TSZ + off);
            }
            // B fragments: 4 n16 pairs -> 8 n8 tiles
            #pragma unroll
            for (int np = 0; np < 4; np++) {
                int r   = wc * 64 + np * 16 + b_r;
                int c16 = kk * 2 + b_c;
                uint32_t off = (uint32_t)(r * 128 + ((c16 ^ (r & 7)) << 4));
                uint32_t bh[4], bl[4];
                LDSM_X4(bh, sb + 2 * TSZ + off);
                LDSM_X4(bl, sb + 3 * TSZ + off);
                #pragma unroll
                for (int mt = 0; mt < 2; mt++) {
                    #pragma unroll
                    for (int h = 0; h < 2; h++) {
                        float* D = acc[mt][np * 2 + h];
                        MMA16816(D, ahi[mt], bh[h*2], bh[h*2+1]);   // hi*hi
                        MMA16816(D, ahi[mt], bl[h*2], bl[h*2+1]);   // hi*lo
                        MMA16816(D, alo[mt], bh[h*2], bh[h*2+1]);   // lo*hi
                    }
                }
            }
        }
        __syncthreads();
    }

    // ---- epilogue: row max over this warp's 64 cols ----
    // acc[mt][nt]: lane holds (r=lane>>2): {row, c}, {row, c+1}, {row+8, c}, {row+8, c+1}
    float mx[4];   // slots: (mt=0,lo8),(mt=0,hi8),(mt=1,lo8),(mt=1,hi8)
    #pragma unroll
    for (int mt = 0; mt < 2; mt++) {
        float m0 = -3.0e38f, m1 = -3.0e38f;
        #pragma unroll
        for (int nt = 0; nt < 8; nt++) {
            m0 = fmaxf(m0, fmaxf(acc[mt][nt][0], acc[mt][nt][1]));
            m1 = fmaxf(m1, fmaxf(acc[mt][nt][2], acc[mt][nt][3]));
        }
        mx[mt * 2 + 0] = m0;
        mx[mt * 2 + 1] = m1;
    }
    // reduce across the 4 lanes of each quad (same row group)
    #pragma unroll
    for (int o = 1; o <= 2; o <<= 1) {
        #pragma unroll
        for (int s = 0; s < 4; s++)
            mx[s] = fmaxf(mx[s], __shfl_xor_sync(0xffffffffu, mx[s], o));
    }
    if ((lane & 3) == 0) {
        int r = lane >> 2;
        #pragma unroll
        for (int s = 0; s < 4; s++) {
            int row = wr * 32 + (s >> 1) * 16 + (s & 1) * 8 + r;
            red[row * 2 + wc] = mx[s];
        }
    }
    __syncthreads();

    float total = 0.0f;
    if (tid < 128)
        total = fmaxf(red[tid * 2], red[tid * 2 + 1]);
    #pragma unroll
    for (int o = 16; o > 0; o >>= 1) total += __shfl_xor_sync(0xffffffffu, total, o);
    if (tid < 128 && lane == 0) wsum[wid] = total;
    __syncthreads();
    if (tid == 0)
        g_scores[(b * NCH + i) * NCH + j] = wsum[0] + wsum[1] + wsum[2] + wsum[3];
}

// ============================================================
// 3) Top-(K-1) selection + weights per (b,i). Serial, tiny.
// ============================================================
__global__ void topk_k() {
    if (threadIdx.x != 0) return;
    int i = blockIdx.x, b = blockIdx.y;
    const float* srow = g_scores + (b * NCH + i) * NCH;

    int num_sel = i < 7 ? i : 7;
    int shift   = 7 - num_sel;

    int   idxs[7];
    float vals[7];
    bool  used[NCH];
    for (int t = 0; t < NCH; t++) used[t] = false;

    for (int r = 0; r < num_sel; r++) {
        float best = -3.0e38f; int bi = 0;
        for (int jj = 0; jj < i; jj++) {
            if (used[jj]) continue;
            float v = srow[jj];
            if (v > best) { best = v; bi = jj; }
        }
        used[bi] = true; idxs[r] = bi; vals[r] = best;
    }

    float vmin = (num_sel > 0) ? vals[num_sel - 1] : 0.0f;
    int base = (b * NCH + i) * KT;
    for (int slot = 0; slot < 7; slot++) {
        if (slot >= shift) {
            int r = slot - shift;
            g_src[base + slot] = idxs[r];
            g_wgt[base + slot] = vals[r] / (vmin + 1e-6f);
        } else {
            g_src[base + slot] = i;
            g_wgt[base + slot] = 0.0f;
        }
    }
    g_src[base + 7] = i;
    g_wgt[base + 7] = 1.0f;
}

// ============================================================
// 4) Output: per (b,i,half): out[128,128] =
//    sum_slots w_s * dp[:, slot*128:+128] @ x[b, src_s] + x_chunk   (fp32 SIMT)
// ============================================================
__global__ void out_k(const float* __restrict__ x, const float* __restrict__ dp,
                      float* __restrict__ out) {
    int half = blockIdx.x, i = blockIdx.y, b = blockIdx.z;
    int e0 = half * 128;

    __shared__ float As[16][132];
    __shared__ float Bs[16][132];
    __shared__ int   s_src[KT];
    __shared__ float s_w[KT];

    int tid = threadIdx.x;
    int tx = tid & 15, ty = tid >> 4;

    if (tid < KT) {
        s_src[tid] = g_src[(b * NCH + i) * KT + tid];
        s_w[tid]   = g_wgt[(b * NCH + i) * KT + tid];
    }
    __syncthreads();

    float acc[8][8];
    #pragma unroll
    for (int u = 0; u < 8; u++)
        #pragma unroll
        for (int v = 0; v < 8; v++) acc[u][v] = 0.0f;

    for (int s = 0; s < KT; s++) {
        float w = s_w[s];
        if (w == 0.0f) continue;
        const float* Bsrc = x + (((size_t)b * TT + (size_t)s_src[s] * CSZ) * EE) + e0;

        for (int k0 = 0; k0 < CSZ; k0 += 16) {
            #pragma unroll
            for (int it = 0; it < 2; it++) {
                int f   = tid + it * 256;
                int row = f >> 2;
                int kq  = (f & 3) * 4;
                float4 va = *(const float4*)(dp + (size_t)row * 1024 + s * 128 + k0 + kq);
                As[kq+0][row] = va.x; As[kq+1][row] = va.y;
                As[kq+2][row] = va.z; As[kq+3][row] = va.w;
            }
            #pragma unroll
            for (int it = 0; it < 2; it++) {
                int f  = tid + it * 256;
                int r  = f >> 5;
                int c4 = (f & 31) * 4;
                float4 vb = *(const float4*)(Bsrc + (size_t)(k0 + r) * EE + c4);
                *(float4*)&Bs[r][c4] = make_float4(w*vb.x, w*vb.y, w*vb.z, w*vb.w);
            }
            __syncthreads();
            #pragma unroll
            for (int k = 0; k < 16; k++) {
                float a[8], bb[8];
                *(float4*)&a[0]  = *(const float4*)&As[k][ty * 8];
                *(float4*)&a[4]  = *(const float4*)&As[k][ty * 8 + 4];
                *(float4*)&bb[0] = *(const float4*)&Bs[k][tx * 8];
                *(float4*)&bb[4] = *(const float4*)&Bs[k][tx * 8 + 4];
                #pragma unroll
                for (int u = 0; u < 8; u++)
                    #pragma unroll
                    for (int v = 0; v < 8; v++)
                        acc[u][v] = fmaf(a[u], bb[v], acc[u][v]);
            }
            __syncthreads();
        }
    }

    size_t obase = ((size_t)b * TT + (size_t)i * CSZ) * EE + e0;
    #pragma unroll
    for (int u = 0; u < 8; u++) {
        int row = ty * 8 + u;
        int col = tx * 8;
        const float4* xc = (const float4*)(x   + obase + (size_t)row * EE + col);
        float4*       oc = (float4*)      (out + obase + (size_t)row * EE + col);
        float4 x0 = xc[0], x1 = xc[1];
        oc[0] = make_float4(acc[u][0] + x0.x, acc[u][1] + x0.y,
                            acc[u][2] + x0.z, acc[u][3] + x0.w);
        oc[1] = make_float4(acc[u][4] + x1.x, acc[u][5] + x1.y,
                            acc[u][6] + x1.z, acc[u][7] + x1.w);
    }
}

// ============================================================
extern "C" void kernel_launch(void* const* d_in, const int* in_sizes, int n_in,
                              void* d_out, int out_size) {
    const float* x  = (const float*)d_in[0];   // [B, T, E] fp32
    const float* dp = (const float*)d_in[1];   // [CS, L] fp32
    float* out = (float*)d_out;

    const int SC_SMEM = 4 * 16384 + 1024 + 64;   // tiles + red + wsum
    cudaFuncSetAttribute(score_hmma_k, cudaFuncAttributeMaxDynamicSharedMemorySize, SC_SMEM);

    normalize_k<<<(BB * TT) / 8, 256>>>(x);
    score_hmma_k<<<dim3(NCH, NCH, BB), 256, SC_SMEM>>>();
    topk_k<<<dim3(NCH, BB), 32>>>();
    out_k<<<dim3(2, NCH, BB), 256>>>(x, dp, out);
}

// round 7
// speedup vs baseline: 2.9081x; 1.4523x over previous
#include <cuda_runtime.h>
#include <cuda_bf16.h>
#include <math.h>
#include <stdint.h>

#define BB  2
#define TT  8192
#define EE  256
#define CSZ 128
#define NCH 64      // TT / CSZ
#define KT  8       // K slots (7 retrieved + current)

// ---- scratch (device globals; no allocation allowed) ----
__device__ __nv_bfloat16 g_hi[(size_t)BB * TT * EE];   // bf16 hi of normalized rows
__device__ __nv_bfloat16 g_lo[(size_t)BB * TT * EE];   // bf16 residual
__device__ __nv_bfloat16 g_dph[CSZ * 1024];            // down_proj hi
__device__ __nv_bfloat16 g_dpl[CSZ * 1024];            // down_proj lo
__device__ float g_scores[BB * NCH * NCH];
__device__ int   g_src[BB * NCH * KT];
__device__ float g_wgt[BB * NCH * KT];

// ================= helpers =================
__device__ __forceinline__ uint32_t smem_u32(const void* p) {
    uint32_t a;
    asm("{ .reg .u64 t; cvta.to.shared.u64 t, %1; cvt.u32.u64 %0, t; }" : "=r"(a) : "l"(p));
    return a;
}
#define LDSM_X4(R, a) \
    asm volatile("ldmatrix.sync.aligned.m8n8.x4.shared.b16 {%0,%1,%2,%3}, [%4];" \
        : "=r"((R)[0]), "=r"((R)[1]), "=r"((R)[2]), "=r"((R)[3]) : "r"(a))
#define LDSM_X4_T(R, a) \
    asm volatile("ldmatrix.sync.aligned.m8n8.x4.trans.shared.b16 {%0,%1,%2,%3}, [%4];" \
        : "=r"((R)[0]), "=r"((R)[1]), "=r"((R)[2]), "=r"((R)[3]) : "r"(a))
#define MMA16816(D, A, B0, B1) \
    asm volatile("mma.sync.aligned.m16n8k16.row.col.f32.bf16.bf16.f32 " \
        "{%0,%1,%2,%3}, {%4,%5,%6,%7}, {%8,%9}, {%0,%1,%2,%3};" \
        : "+f"((D)[0]), "+f"((D)[1]), "+f"((D)[2]), "+f"((D)[3]) \
        : "r"((A)[0]), "r"((A)[1]), "r"((A)[2]), "r"((A)[3]), "r"(B0), "r"(B1))

// ============================================================
// 1) Row normalization -> bf16 hi/lo split of cn
// ============================================================
__global__ void normalize_k(const float* __restrict__ x) {
    int row  = blockIdx.x * 8 + (threadIdx.x >> 5);
    int lane = threadIdx.x & 31;
    const float4* xr = (const float4*)(x + (size_t)row * EE);
    float4 v0 = xr[lane];
    float4 v1 = xr[lane + 32];
    float ss = v0.x*v0.x + v0.y*v0.y + v0.z*v0.z + v0.w*v0.w
             + v1.x*v1.x + v1.y*v1.y + v1.z*v1.z + v1.w*v1.w;
    #pragma unroll
    for (int o = 16; o > 0; o >>= 1) ss += __shfl_xor_sync(0xffffffffu, ss, o);
    float inv = 1.0f / (sqrtf(ss) + 1e-6f);

    float f[8] = { v0.x*inv, v0.y*inv, v0.z*inv, v0.w*inv,
                   v1.x*inv, v1.y*inv, v1.z*inv, v1.w*inv };
    __nv_bfloat16 h[8], l[8];
    #pragma unroll
    for (int t = 0; t < 8; t++) {
        h[t] = __float2bfloat16(f[t]);
        l[t] = __float2bfloat16(f[t] - __bfloat162float(h[t]));
    }
    size_t base = (size_t)row * EE;
    uint32_t* hp = (uint32_t*)(g_hi + base);
    uint32_t* lp = (uint32_t*)(g_lo + base);
    #pragma unroll
    for (int t = 0; t < 2; t++) {
        int eb = t * 64 + lane * 2;
        __nv_bfloat162 hh0(h[t*4+0], h[t*4+1]), hh1(h[t*4+2], h[t*4+3]);
        __nv_bfloat162 ll0(l[t*4+0], l[t*4+1]), ll1(l[t*4+2], l[t*4+3]);
        hp[eb]     = *(uint32_t*)&hh0;
        hp[eb + 1] = *(uint32_t*)&hh1;
        lp[eb]     = *(uint32_t*)&ll0;
        lp[eb + 1] = *(uint32_t*)&ll1;
    }
}

// ============================================================
// 1b) dp hi/lo split: [128 x 1024] fp32 -> bf16 hi + lo
// ============================================================
__global__ void dp_prep_k(const float* __restrict__ dp) {
    int idx = (blockIdx.x * 256 + threadIdx.x) * 4;   // grid 128, 4 elems/thread
    float4 v = *(const float4*)(dp + idx);
    float f[4] = { v.x, v.y, v.z, v.w };
    __nv_bfloat16 h[4], l[4];
    #pragma unroll
    for (int t = 0; t < 4; t++) {
        h[t] = __float2bfloat16(f[t]);
        l[t] = __float2bfloat16(f[t] - __bfloat162float(h[t]));
    }
    __nv_bfloat162 hh0(h[0], h[1]), hh1(h[2], h[3]);
    __nv_bfloat162 ll0(l[0], l[1]), ll1(l[2], l[3]);
    uint32_t* hp = (uint32_t*)(g_dph + idx);
    uint32_t* lp = (uint32_t*)(g_dpl + idx);
    hp[0] = *(uint32_t*)&hh0;  hp[1] = *(uint32_t*)&hh1;
    lp[0] = *(uint32_t*)&ll0;  lp[1] = *(uint32_t*)&ll1;
}

// ============================================================
// 2) Score kernel via mma.sync bf16x3 (unchanged from R6 pass)
// ============================================================
__global__ void __launch_bounds__(256, 2)
score_hmma_k() {
    int j = blockIdx.x, i = blockIdx.y, b = blockIdx.z;
    if (j >= i) return;

    extern __shared__ char smem[];
    uint32_t sb = smem_u32(smem);
    const uint32_t TSZ = 16384;
    float* red  = (float*)(smem + 4 * TSZ);
    float* wsum = (float*)(smem + 4 * TSZ + 1024);

    int tid  = threadIdx.x;
    int wid  = tid >> 5;
    int lane = tid & 31;
    int wr = wid >> 1;
    int wc = wid & 1;

    const __nv_bfloat16* srcp[4] = {
        g_hi + ((size_t)(b * NCH + i) * CSZ) * EE,
        g_lo + ((size_t)(b * NCH + i) * CSZ) * EE,
        g_hi + ((size_t)(b * NCH + j) * CSZ) * EE,
        g_lo + ((size_t)(b * NCH + j) * CSZ) * EE
    };

    float acc[2][8][4];
    #pragma unroll
    for (int mt = 0; mt < 2; mt++)
        #pragma unroll
        for (int nt = 0; nt < 8; nt++)
            #pragma unroll
            for (int e = 0; e < 4; e++) acc[mt][nt][e] = 0.0f;

    int a_r = (lane & 15);
    int a_c = (lane >> 4);
    int b_r = (lane & 7) + ((lane >> 4) << 3);
    int b_c = (lane >> 3) & 1;

    for (int c = 0; c < 4; c++) {
        int k0 = c * 64;
        #pragma unroll
        for (int t = 0; t < 4; t++) {
            const __nv_bfloat16* s = srcp[t] + k0;
            char* tb = smem + t * TSZ;
            #pragma unroll
            for (int q = 0; q < 4; q++) {
                int idx = q * 256 + tid;
                int r   = idx >> 3;
                int c8  = idx & 7;
                uint4 v = *(const uint4*)(s + (size_t)r * EE + c8 * 8);
                *(uint4*)(tb + r * 128 + ((c8 ^ (r & 7)) << 4)) = v;
            }
        }
        __syncthreads();

        #pragma unroll
        for (int kk = 0; kk < 4; kk++) {
            uint32_t ahi[2][4], alo[2][4];
            #pragma unroll
            for (int mt = 0; mt < 2; mt++) {
                int r   = wr * 32 + mt * 16 + a_r;
                int c16 = kk * 2 + a_c;
                uint32_t off = (uint32_t)(r * 128 + ((c16 ^ (r & 7)) << 4));
                LDSM_X4(ahi[mt], sb + 0 * TSZ + off);
                LDSM_X4(alo[mt], sb + 1 * TSZ + off);
            }
            #pragma unroll
            for (int np = 0; np < 4; np++) {
                int r   = wc * 64 + np * 16 + b_r;
                int c16 = kk * 2 + b_c;
                uint32_t off = (uint32_t)(r * 128 + ((c16 ^ (r & 7)) << 4));
                uint32_t bh[4], bl[4];
                LDSM_X4(bh, sb + 2 * TSZ + off);
                LDSM_X4(bl, sb + 3 * TSZ + off);
                #pragma unroll
                for (int mt = 0; mt < 2; mt++) {
                    #pragma unroll
                    for (int h = 0; h < 2; h++) {
                        float* D = acc[mt][np * 2 + h];
                        MMA16816(D, ahi[mt], bh[h*2], bh[h*2+1]);
                        MMA16816(D, ahi[mt], bl[h*2], bl[h*2+1]);
                        MMA16816(D, alo[mt], bh[h*2], bh[h*2+1]);
                    }
                }
            }
        }
        __syncthreads();
    }

    float mx[4];
    #pragma unroll
    for (int mt = 0; mt < 2; mt++) {
        float m0 = -3.0e38f, m1 = -3.0e38f;
        #pragma unroll
        for (int nt = 0; nt < 8; nt++) {
            m0 = fmaxf(m0, fmaxf(acc[mt][nt][0], acc[mt][nt][1]));
            m1 = fmaxf(m1, fmaxf(acc[mt][nt][2], acc[mt][nt][3]));
        }
        mx[mt * 2 + 0] = m0;
        mx[mt * 2 + 1] = m1;
    }
    #pragma unroll
    for (int o = 1; o <= 2; o <<= 1) {
        #pragma unroll
        for (int s = 0; s < 4; s++)
            mx[s] = fmaxf(mx[s], __shfl_xor_sync(0xffffffffu, mx[s], o));
    }
    if ((lane & 3) == 0) {
        int r = lane >> 2;
        #pragma unroll
        for (int s = 0; s < 4; s++) {
            int row = wr * 32 + (s >> 1) * 16 + (s & 1) * 8 + r;
            red[row * 2 + wc] = mx[s];
        }
    }
    __syncthreads();

    float total = 0.0f;
    if (tid < 128)
        total = fmaxf(red[tid * 2], red[tid * 2 + 1]);
    #pragma unroll
    for (int o = 16; o > 0; o >>= 1) total += __shfl_xor_sync(0xffffffffu, total, o);
    if (tid < 128 && lane == 0) wsum[wid] = total;
    __syncthreads();
    if (tid == 0)
        g_scores[(b * NCH + i) * NCH + j] = wsum[0] + wsum[1] + wsum[2] + wsum[3];
}

// ============================================================
// 3) Top-(K-1) selection + weights per (b,i). Serial, tiny.
// ============================================================
__global__ void topk_k() {
    if (threadIdx.x != 0) return;
    int i = blockIdx.x, b = blockIdx.y;
    const float* srow = g_scores + (b * NCH + i) * NCH;

    int num_sel = i < 7 ? i : 7;
    int shift   = 7 - num_sel;

    int   idxs[7];
    float vals[7];
    bool  used[NCH];
    for (int t = 0; t < NCH; t++) used[t] = false;

    for (int r = 0; r < num_sel; r++) {
        float best = -3.0e38f; int bi = 0;
        for (int jj = 0; jj < i; jj++) {
            if (used[jj]) continue;
            float v = srow[jj];
            if (v > best) { best = v; bi = jj; }
        }
        used[bi] = true; idxs[r] = bi; vals[r] = best;
    }

    float vmin = (num_sel > 0) ? vals[num_sel - 1] : 0.0f;
    int base = (b * NCH + i) * KT;
    for (int slot = 0; slot < 7; slot++) {
        if (slot >= shift) {
            int r = slot - shift;
            g_src[base + slot] = idxs[r];
            g_wgt[base + slot] = vals[r] / (vmin + 1e-6f);
        } else {
            g_src[base + slot] = i;
            g_wgt[base + slot] = 0.0f;
        }
    }
    g_src[base + 7] = i;
    g_wgt[base + 7] = 1.0f;
}

// ============================================================
// 4) Output GEMM via mma.sync bf16x3. One CTA (8 warps) per (b,i).
//    C[128,256] = sum_s dp[:, s*128:+128] @ (w_s * x[b,src_s])  + x_chunk
//    A = dp hi/lo (non-trans ldmatrix, rows=c), B = w*x hi/lo
//    (x natural [k][e] layout consumed via ldmatrix.trans, rows=k).
// smem: Ah[16K] Al[16K] Bh[32K] Bl[32K] = 96 KB
// ============================================================
__global__ void __launch_bounds__(256, 1)
out_hmma_k(const float* __restrict__ x, float* __restrict__ out) {
    int i = blockIdx.x, b = blockIdx.y;

    extern __shared__ char smem[];
    uint32_t sb = smem_u32(smem);
    const uint32_t AH = 0, AL = 16384, BH = 32768, BL = 65536;

    __shared__ int   s_src[KT];
    __shared__ float s_w[KT];

    int tid  = threadIdx.x;
    int wid  = tid >> 5;
    int lane = tid & 31;
    int wr = wid >> 2;      // 0..1 : rows [wr*64, +64)
    int wc = wid & 3;       // 0..3 : cols [wc*64, +64)

    if (tid < KT) {
        s_src[tid] = g_src[(b * NCH + i) * KT + tid];
        s_w[tid]   = g_wgt[(b * NCH + i) * KT + tid];
    }
    __syncthreads();

    float acc[4][8][4];   // mt(4 x m16) x nt(8 x n8) x frag4
    #pragma unroll
    for (int mt = 0; mt < 4; mt++)
        #pragma unroll
        for (int nt = 0; nt < 8; nt++)
            #pragma unroll
            for (int e = 0; e < 4; e++) acc[mt][nt][e] = 0.0f;

    // ldmatrix lane address components
    int a_r = (lane & 15);              // A: row within m16
    int a_c = (lane >> 4);              // A: k granule half
    int b_k = (lane & 7) + (((lane >> 3) & 1) << 3);  // B: k row within k16
    int b_g = (lane >> 4);              // B: n granule (0/1 -> n0-7 / n8-15)

    for (int s = 0; s < KT; s++) {
        float w = s_w[s];
        if (w == 0.0f) continue;
        int src = s_src[s];

        for (int kc = 0; kc < 2; kc++) {
            // ---- A tile: dp[c][s*128 + kc*64 + k], 128 rows x 64 cols ----
            {
                int col0 = s * 128 + kc * 64;
                #pragma unroll
                for (int q = 0; q < 4; q++) {
                    int idx = q * 256 + tid;   // 0..1023 granules
                    int r   = idx >> 3;        // row c
                    int gk  = idx & 7;         // k granule
                    uint32_t dst = (uint32_t)(r * 128 + ((gk ^ (r & 7)) << 4));
                    int so = r * 1024 + col0 + gk * 8;
                    *(uint4*)(smem + AH + dst) = *(const uint4*)(g_dph + so);
                    *(uint4*)(smem + AL + dst) = *(const uint4*)(g_dpl + so);
                }
            }
            // ---- B tile: w * x[b, src*128 + kc*64 + k][e], 64 k-rows x 256 e ----
            {
                const float* xb = x + ((size_t)b * TT + (size_t)src * CSZ + kc * 64) * EE;
                #pragma unroll
                for (int q = 0; q < 8; q++) {
                    int idx = q * 256 + tid;   // 0..2047 granules
                    int k   = idx >> 5;        // k row 0..63
                    int g   = idx & 31;        // e granule 0..31
                    const float* xs = xb + (size_t)k * EE + g * 8;
                    float4 v0 = *(const float4*)(xs);
                    float4 v1 = *(const float4*)(xs + 4);
                    float f[8] = { w*v0.x, w*v0.y, w*v0.z, w*v0.w,
                                   w*v1.x, w*v1.y, w*v1.z, w*v1.w };
                    __nv_bfloat16 h[8], l[8];
                    #pragma unroll
                    for (int t = 0; t < 8; t++) {
                        h[t] = __float2bfloat16(f[t]);
                        l[t] = __float2bfloat16(f[t] - __bfloat162float(h[t]));
                    }
                    __nv_bfloat162 hh[4] = { {h[0],h[1]}, {h[2],h[3]}, {h[4],h[5]}, {h[6],h[7]} };
                    __nv_bfloat162 ll[4] = { {l[0],l[1]}, {l[2],l[3]}, {l[4],l[5]}, {l[6],l[7]} };
                    uint32_t dst = (uint32_t)(k * 512 + ((g ^ (k & 7)) << 4));
                    *(uint4*)(smem + BH + dst) = *(uint4*)hh;
                    *(uint4*)(smem + BL + dst) = *(uint4*)ll;
                }
            }
            __syncthreads();

            #pragma unroll
            for (int kk = 0; kk < 4; kk++) {
                uint32_t ahi[4][4], alo[4][4];
                #pragma unroll
                for (int mt = 0; mt < 4; mt++) {
                    int r   = wr * 64 + mt * 16 + a_r;
                    int c16 = kk * 2 + a_c;
                    uint32_t off = (uint32_t)(r * 128 + ((c16 ^ (r & 7)) << 4));
                    LDSM_X4(ahi[mt], sb + AH + off);
                    LDSM_X4(alo[mt], sb + AL + off);
                }
                #pragma unroll
                for (int np = 0; np < 4; np++) {
                    int k = kk * 16 + b_k;
                    int g = (wc * 8 + np * 2) + b_g;
                    uint32_t off = (uint32_t)(k * 512 + ((g ^ (k & 7)) << 4));
                    uint32_t bh[4], bl[4];
                    LDSM_X4_T(bh, sb + BH + off);
                    LDSM_X4_T(bl, sb + BL + off);
                    #pragma unroll
                    for (int mt = 0; mt < 4; mt++) {
                        #pragma unroll
                        for (int h = 0; h < 2; h++) {
                            float* D = acc[mt][np * 2 + h];
                            MMA16816(D, ahi[mt], bh[h*2], bh[h*2+1]);
                            MMA16816(D, ahi[mt], bl[h*2], bl[h*2+1]);
                            MMA16816(D, alo[mt], bh[h*2], bh[h*2+1]);
                        }
                    }
                }
            }
            __syncthreads();
        }
    }

    // ---- epilogue: += residual x chunk, store ----
    size_t obase = ((size_t)b * TT + (size_t)i * CSZ) * EE;
    int qr = lane >> 2, qc = (lane & 3) * 2;
    #pragma unroll
    for (int mt = 0; mt < 4; mt++) {
        #pragma unroll
        for (int nt = 0; nt < 8; nt++) {
            int col = wc * 64 + nt * 8 + qc;
            #pragma unroll
            for (int h = 0; h < 2; h++) {
                int row = wr * 64 + mt * 16 + h * 8 + qr;
                size_t o = obase + (size_t)row * EE + col;
                float2 xr = *(const float2*)(x + o);
                float2 r;
                r.x = acc[mt][nt][h*2 + 0] + xr.x;
                r.y = acc[mt][nt][h*2 + 1] + xr.y;
                *(float2*)(out + o) = r;
            }
        }
    }
}

// ============================================================
extern "C" void kernel_launch(void* const* d_in, const int* in_sizes, int n_in,
                              void* d_out, int out_size) {
    const float* x  = (const float*)d_in[0];   // [B, T, E] fp32
    const float* dp = (const float*)d_in[1];   // [CS, L] fp32
    float* out = (float*)d_out;

    const int SC_SMEM  = 4 * 16384 + 1024 + 64;
    const int OUT_SMEM = 96 * 1024;
    cudaFuncSetAttribute(score_hmma_k, cudaFuncAttributeMaxDynamicSharedMemorySize, SC_SMEM);
    cudaFuncSetAttribute(out_hmma_k,   cudaFuncAttributeMaxDynamicSharedMemorySize, OUT_SMEM);

    normalize_k<<<(BB * TT) / 8, 256>>>(x);
    dp_prep_k<<<CSZ, 256>>>(dp);
    score_hmma_k<<<dim3(NCH, NCH, BB), 256, SC_SMEM>>>();
    topk_k<<<dim3(NCH, BB), 32>>>();
    out_hmma_k<<<dim3(NCH, BB), 256, OUT_SMEM>>>(x, out);
}

// round 9
// speedup vs baseline: 3.0195x; 1.0383x over previous
#include <cuda_runtime.h>
#include <cuda_bf16.h>
#include <math.h>
#include <stdint.h>

#define BB  2
#define TT  8192
#define EE  256
#define CSZ 128
#define NCH 64      // TT / CSZ
#define KT  8       // K slots (7 retrieved + current)

// ---- scratch (device globals; no allocation allowed) ----
__device__ __nv_bfloat16 g_hi[(size_t)BB * TT * EE];   // bf16 hi of normalized rows
__device__ __nv_bfloat16 g_lo[(size_t)BB * TT * EE];   // bf16 residual (normalized)
__device__ __nv_bfloat16 g_xh[(size_t)BB * TT * EE];   // bf16 hi of raw x
__device__ __nv_bfloat16 g_xl[(size_t)BB * TT * EE];   // bf16 residual of raw x
__device__ float g_scores[BB * NCH * NCH];
__device__ int   g_src[BB * NCH * KT];
__device__ float g_wgt[BB * NCH * KT];

// ================= helpers =================
__device__ __forceinline__ uint32_t smem_u32(const void* p) {
    uint32_t a;
    asm("{ .reg .u64 t; cvta.to.shared.u64 t, %1; cvt.u32.u64 %0, t; }" : "=r"(a) : "l"(p));
    return a;
}
__device__ __forceinline__ void cp_async16(uint32_t dst, const void* src) {
    asm volatile("cp.async.cg.shared.global [%0], [%1], 16;" :: "r"(dst), "l"(src));
}
#define CP_ASYNC_COMMIT() asm volatile("cp.async.commit_group;" ::: "memory")
#define CP_ASYNC_WAIT0()  asm volatile("cp.async.wait_group 0;"  ::: "memory")
#define LDSM_X4(R, a) \
    asm volatile("ldmatrix.sync.aligned.m8n8.x4.shared.b16 {%0,%1,%2,%3}, [%4];" \
        : "=r"((R)[0]), "=r"((R)[1]), "=r"((R)[2]), "=r"((R)[3]) : "r"(a))
#define LDSM_X4_T(R, a) \
    asm volatile("ldmatrix.sync.aligned.m8n8.x4.trans.shared.b16 {%0,%1,%2,%3}, [%4];" \
        : "=r"((R)[0]), "=r"((R)[1]), "=r"((R)[2]), "=r"((R)[3]) : "r"(a))
#define MMA16816(D, A, B0, B1) \
    asm volatile("mma.sync.aligned.m16n8k16.row.col.f32.bf16.bf16.f32 " \
        "{%0,%1,%2,%3}, {%4,%5,%6,%7}, {%8,%9}, {%0,%1,%2,%3};" \
        : "+f"((D)[0]), "+f"((D)[1]), "+f"((D)[2]), "+f"((D)[3]) \
        : "r"((A)[0]), "r"((A)[1]), "r"((A)[2]), "r"((A)[3]), "r"(B0), "r"(B1))

// ============================================================
// 1) Row normalization -> bf16 hi/lo of cn, plus bf16 hi/lo of raw x
// ============================================================
__global__ void normalize_k(const float* __restrict__ x) {
    int row  = blockIdx.x * 8 + (threadIdx.x >> 5);
    int lane = threadIdx.x & 31;
    const float4* xr = (const float4*)(x + (size_t)row * EE);
    float4 v0 = xr[lane];
    float4 v1 = xr[lane + 32];
    float ss = v0.x*v0.x + v0.y*v0.y + v0.z*v0.z + v0.w*v0.w
             + v1.x*v1.x + v1.y*v1.y + v1.z*v1.z + v1.w*v1.w;
    #pragma unroll
    for (int o = 16; o > 0; o >>= 1) ss += __shfl_xor_sync(0xffffffffu, ss, o);
    float inv = 1.0f / (sqrtf(ss) + 1e-6f);

    float fr[8] = { v0.x, v0.y, v0.z, v0.w, v1.x, v1.y, v1.z, v1.w };
    size_t base = (size_t)row * EE;
    uint32_t* hp = (uint32_t*)(g_hi + base);
    uint32_t* lp = (uint32_t*)(g_lo + base);
    uint32_t* xhp = (uint32_t*)(g_xh + base);
    uint32_t* xlp = (uint32_t*)(g_xl + base);

    __nv_bfloat16 h[8], l[8], rh[8], rl[8];
    #pragma unroll
    for (int t = 0; t < 8; t++) {
        float fn = fr[t] * inv;
        h[t]  = __float2bfloat16(fn);
        l[t]  = __float2bfloat16(fn - __bfloat162float(h[t]));
        rh[t] = __float2bfloat16(fr[t]);
        rl[t] = __float2bfloat16(fr[t] - __bfloat162float(rh[t]));
    }
    #pragma unroll
    for (int t = 0; t < 2; t++) {
        int eb = t * 64 + lane * 2;
        __nv_bfloat162 a0(h[t*4+0], h[t*4+1]),  a1(h[t*4+2], h[t*4+3]);
        __nv_bfloat162 b0(l[t*4+0], l[t*4+1]),  b1(l[t*4+2], l[t*4+3]);
        __nv_bfloat162 c0(rh[t*4+0], rh[t*4+1]), c1(rh[t*4+2], rh[t*4+3]);
        __nv_bfloat162 d0(rl[t*4+0], rl[t*4+1]), d1(rl[t*4+2], rl[t*4+3]);
        hp[eb]  = *(uint32_t*)&a0;  hp[eb+1]  = *(uint32_t*)&a1;
        lp[eb]  = *(uint32_t*)&b0;  lp[eb+1]  = *(uint32_t*)&b1;
        xhp[eb] = *(uint32_t*)&c0;  xhp[eb+1] = *(uint32_t*)&c1;
        xlp[eb] = *(uint32_t*)&d0;  xlp[eb+1] = *(uint32_t*)&d1;
    }
}

// ============================================================
// 2) Score kernel via mma.sync bf16x3 (unchanged — validated R6)
// ============================================================
__global__ void __launch_bounds__(256, 2)
score_hmma_k() {
    int j = blockIdx.x, i = blockIdx.y, b = blockIdx.z;
    if (j >= i) return;

    extern __shared__ char smem[];
    uint32_t sb = smem_u32(smem);
    const uint32_t TSZ = 16384;
    float* red  = (float*)(smem + 4 * TSZ);
    float* wsum = (float*)(smem + 4 * TSZ + 1024);

    int tid  = threadIdx.x;
    int wid  = tid >> 5;
    int lane = tid & 31;
    int wr = wid >> 1;
    int wc = wid & 1;

    const __nv_bfloat16* srcp[4] = {
        g_hi + ((size_t)(b * NCH + i) * CSZ) * EE,
        g_lo + ((size_t)(b * NCH + i) * CSZ) * EE,
        g_hi + ((size_t)(b * NCH + j) * CSZ) * EE,
        g_lo + ((size_t)(b * NCH + j) * CSZ) * EE
    };

    float acc[2][8][4];
    #pragma unroll
    for (int mt = 0; mt < 2; mt++)
        #pragma unroll
        for (int nt = 0; nt < 8; nt++)
            #pragma unroll
            for (int e = 0; e < 4; e++) acc[mt][nt][e] = 0.0f;

    int a_r = (lane & 15);
    int a_c = (lane >> 4);
    int b_r = (lane & 7) + ((lane >> 4) << 3);
    int b_c = (lane >> 3) & 1;

    for (int c = 0; c < 4; c++) {
        int k0 = c * 64;
        #pragma unroll
        for (int t = 0; t < 4; t++) {
            const __nv_bfloat16* s = srcp[t] + k0;
            char* tb = smem + t * TSZ;
            #pragma unroll
            for (int q = 0; q < 4; q++) {
                int idx = q * 256 + tid;
                int r   = idx >> 3;
                int c8  = idx & 7;
                uint4 v = *(const uint4*)(s + (size_t)r * EE + c8 * 8);
                *(uint4*)(tb + r * 128 + ((c8 ^ (r & 7)) << 4)) = v;
            }
        }
        __syncthreads();

        #pragma unroll
        for (int kk = 0; kk < 4; kk++) {
            uint32_t ahi[2][4], alo[2][4];
            #pragma unroll
            for (int mt = 0; mt < 2; mt++) {
                int r   = wr * 32 + mt * 16 + a_r;
                int c16 = kk * 2 + a_c;
                uint32_t off = (uint32_t)(r * 128 + ((c16 ^ (r & 7)) << 4));
                LDSM_X4(ahi[mt], sb + 0 * TSZ + off);
                LDSM_X4(alo[mt], sb + 1 * TSZ + off);
            }
            #pragma unroll
            for (int np = 0; np < 4; np++) {
                int r   = wc * 64 + np * 16 + b_r;
                int c16 = kk * 2 + b_c;
                uint32_t off = (uint32_t)(r * 128 + ((c16 ^ (r & 7)) << 4));
                uint32_t bh[4], bl[4];
                LDSM_X4(bh, sb + 2 * TSZ + off);
                LDSM_X4(bl, sb + 3 * TSZ + off);
                #pragma unroll
                for (int mt = 0; mt < 2; mt++) {
                    #pragma unroll
                    for (int h = 0; h < 2; h++) {
                        float* D = acc[mt][np * 2 + h];
                        MMA16816(D, ahi[mt], bh[h*2], bh[h*2+1]);
                        MMA16816(D, ahi[mt], bl[h*2], bl[h*2+1]);
                        MMA16816(D, alo[mt], bh[h*2], bh[h*2+1]);
                    }
                }
            }
        }
        __syncthreads();
    }

    float mx[4];
    #pragma unroll
    for (int mt = 0; mt < 2; mt++) {
        float m0 = -3.0e38f, m1 = -3.0e38f;
        #pragma unroll
        for (int nt = 0; nt < 8; nt++) {
            m0 = fmaxf(m0, fmaxf(acc[mt][nt][0], acc[mt][nt][1]));
            m1 = fmaxf(m1, fmaxf(acc[mt][nt][2], acc[mt][nt][3]));
        }
        mx[mt * 2 + 0] = m0;
        mx[mt * 2 + 1] = m1;
    }
    #pragma unroll
    for (int o = 1; o <= 2; o <<= 1) {
        #pragma unroll
        for (int s = 0; s < 4; s++)
            mx[s] = fmaxf(mx[s], __shfl_xor_sync(0xffffffffu, mx[s], o));
    }
    if ((lane & 3) == 0) {
        int r = lane >> 2;
        #pragma unroll
        for (int s = 0; s < 4; s++) {
            int row = wr * 32 + (s >> 1) * 16 + (s & 1) * 8 + r;
            red[row * 2 + wc] = mx[s];
        }
    }
    __syncthreads();

    float total = 0.0f;
    if (tid < 128)
        total = fmaxf(red[tid * 2], red[tid * 2 + 1]);
    #pragma unroll
    for (int o = 16; o > 0; o >>= 1) total += __shfl_xor_sync(0xffffffffu, total, o);
    if (tid < 128 && lane == 0) wsum[wid] = total;
    __syncthreads();
    if (tid == 0)
        g_scores[(b * NCH + i) * NCH + j] = wsum[0] + wsum[1] + wsum[2] + wsum[3];
}

// ============================================================
// 3) Top-(K-1) selection, warp-parallel per (b,i).
//    Butterfly argmax, lowest index wins ties (matches lax.top_k).
// ============================================================
__global__ void topk_warp_k() {
    int i = blockIdx.x, b = blockIdx.y;
    int lane = threadIdx.x;
    const float* srow = g_scores + (b * NCH + i) * NCH;

    int num_sel = i < 7 ? i : 7;
    int shift   = 7 - num_sel;

    float v0 = (lane      < i) ? srow[lane]      : -3.0e38f;
    float v1 = (lane + 32 < i) ? srow[lane + 32] : -3.0e38f;

    float vals[7];
    int   idxs[7];
    for (int r = 0; r < num_sel; r++) {
        float mv = v0; int mi = lane;
        if (v1 > mv) { mv = v1; mi = lane + 32; }
        #pragma unroll
        for (int o = 16; o > 0; o >>= 1) {
            float ov = __shfl_xor_sync(0xffffffffu, mv, o);
            int   oi = __shfl_xor_sync(0xffffffffu, mi, o);
            if (ov > mv || (ov == mv && oi < mi)) { mv = ov; mi = oi; }
        }
        vals[r] = mv; idxs[r] = mi;
        if (mi == lane)      v0 = -3.0e38f;
        if (mi == lane + 32) v1 = -3.0e38f;
    }

    if (lane == 0) {
        float vmin = (num_sel > 0) ? vals[num_sel - 1] : 0.0f;
        int base = (b * NCH + i) * KT;
        for (int slot = 0; slot < 7; slot++) {
            if (slot >= shift) {
                int r = slot - shift;
                g_src[base + slot] = idxs[r];
                g_wgt[base + slot] = vals[r] / (vmin + 1e-6f);
            } else {
                g_src[base + slot] = i;
                g_wgt[base + slot] = 0.0f;
            }
        }
        g_src[base + 7] = i;
        g_wgt[base + 7] = 1.0f;
    }
}

// ============================================================
// 4) Output GEMM via mma.sync bf16x3. One CTA (8 warps) per (b,i).
//    C[128,256] = sum_s (w_s·dp[:, s*128:+128]) @ x[b,src_s] + x_chunk
//    A = w·dp hi/lo (converted in-kernel), B = raw x hi/lo (precomputed,
//    loaded via cp.async overlapped with A conversion).
// smem: Ah[16K] Al[16K] Bh[32K] Bl[32K] = 96 KB
// ============================================================
__global__ void __launch_bounds__(256, 1)
out_hmma_k(const float* __restrict__ x, const float* __restrict__ dp,
           float* __restrict__ out) {
    int i = blockIdx.x, b = blockIdx.y;

    extern __shared__ char smem[];
    uint32_t sb = smem_u32(smem);
    const uint32_t AH = 0, AL = 16384, BH = 32768, BL = 65536;

    __shared__ int   s_src[KT];
    __shared__ float s_w[KT];

    int tid  = threadIdx.x;
    int wid  = tid >> 5;
    int lane = tid & 31;
    int wr = wid >> 2;      // 0..1 : rows [wr*64, +64)
    int wc = wid & 3;       // 0..3 : cols [wc*64, +64)

    if (tid < KT) {
        s_src[tid] = g_src[(b * NCH + i) * KT + tid];
        s_w[tid]   = g_wgt[(b * NCH + i) * KT + tid];
    }
    __syncthreads();

    float acc[4][8][4];
    #pragma unroll
    for (int mt = 0; mt < 4; mt++)
        #pragma unroll
        for (int nt = 0; nt < 8; nt++)
            #pragma unroll
            for (int e = 0; e < 4; e++) acc[mt][nt][e] = 0.0f;

    int a_r = (lane & 15);
    int a_c = (lane >> 4);
    int b_k = (lane & 7) + (((lane >> 3) & 1) << 3);
    int b_g = (lane >> 4);

    for (int s = 0; s < KT; s++) {
        float w = s_w[s];
        if (w == 0.0f) continue;
        int src = s_src[s];

        for (int kc = 0; kc < 2; kc++) {
            // ---- B tiles via cp.async: 64 k-rows x 256 e, bf16 hi/lo ----
            {
                size_t rb = ((size_t)b * TT + (size_t)src * CSZ + kc * 64) * EE;
                const __nv_bfloat16* xbh = g_xh + rb;
                const __nv_bfloat16* xbl = g_xl + rb;
                #pragma unroll
                for (int q = 0; q < 8; q++) {
                    int idx = q * 256 + tid;   // 0..2047 granules
                    int k   = idx >> 5;        // k row 0..63
                    int g   = idx & 31;        // e granule 0..31
                    uint32_t dst = (uint32_t)(k * 512 + ((g ^ (k & 7)) << 4));
                    cp_async16(sb + BH + dst, xbh + (size_t)k * EE + g * 8);
                    cp_async16(sb + BL + dst, xbl + (size_t)k * EE + g * 8);
                }
                CP_ASYNC_COMMIT();
            }
            // ---- A tile: w * dp[c][s*128 + kc*64 + k], 128 rows x 64 cols ----
            {
                int col0 = s * 128 + kc * 64;
                #pragma unroll
                for (int q = 0; q < 4; q++) {
                    int idx = q * 256 + tid;   // 0..1023 granules
                    int r   = idx >> 3;        // row c
                    int gk  = idx & 7;         // k granule
                    const float* dps = dp + (size_t)r * 1024 + col0 + gk * 8;
                    float4 u0 = *(const float4*)(dps);
                    float4 u1 = *(const float4*)(dps + 4);
                    float f[8] = { w*u0.x, w*u0.y, w*u0.z, w*u0.w,
                                   w*u1.x, w*u1.y, w*u1.z, w*u1.w };
                    __nv_bfloat16 h[8], l[8];
                    #pragma unroll
                    for (int t = 0; t < 8; t++) {
                        h[t] = __float2bfloat16(f[t]);
                        l[t] = __float2bfloat16(f[t] - __bfloat162float(h[t]));
                    }
                    __nv_bfloat162 hh[4] = { {h[0],h[1]}, {h[2],h[3]}, {h[4],h[5]}, {h[6],h[7]} };
                    __nv_bfloat162 ll[4] = { {l[0],l[1]}, {l[2],l[3]}, {l[4],l[5]}, {l[6],l[7]} };
                    uint32_t dst = (uint32_t)(r * 128 + ((gk ^ (r & 7)) << 4));
                    *(uint4*)(smem + AH + dst) = *(uint4*)hh;
                    *(uint4*)(smem + AL + dst) = *(uint4*)ll;
                }
            }
            CP_ASYNC_WAIT0();
            __syncthreads();

            #pragma unroll
            for (int kk = 0; kk < 4; kk++) {
                uint32_t ahi[4][4], alo[4][4];
                #pragma unroll
                for (int mt = 0; mt < 4; mt++) {
                    int r   = wr * 64 + mt * 16 + a_r;
                    int c16 = kk * 2 + a_c;
                    uint32_t off = (uint32_t)(r * 128 + ((c16 ^ (r & 7)) << 4));
                    LDSM_X4(ahi[mt], sb + AH + off);
                    LDSM_X4(alo[mt], sb + AL + off);
                }
                #pragma unroll
                for (int np = 0; np < 4; np++) {
                    int k = kk * 16 + b_k;
                    int g = (wc * 8 + np * 2) + b_g;
                    uint32_t off = (uint32_t)(k * 512 + ((g ^ (k & 7)) << 4));
                    uint32_t bh[4], bl[4];
                    LDSM_X4_T(bh, sb + BH + off);
                    LDSM_X4_T(bl, sb + BL + off);
                    #pragma unroll
                    for (int mt = 0; mt < 4; mt++) {
                        #pragma unroll
                        for (int h = 0; h < 2; h++) {
                            float* D = acc[mt][np * 2 + h];
                            MMA16816(D, ahi[mt], bh[h*2], bh[h*2+1]);
                            MMA16816(D, ahi[mt], bl[h*2], bl[h*2+1]);
                            MMA16816(D, alo[mt], bh[h*2], bh[h*2+1]);
                        }
                    }
                }
            }
            __syncthreads();
        }
    }

    // ---- epilogue: += residual x chunk, store ----
    size_t obase = ((size_t)b * TT + (size_t)i * CSZ) * EE;
    int qr = lane >> 2, qc = (lane & 3) * 2;
    #pragma unroll
    for (int mt = 0; mt < 4; mt++) {
        #pragma unroll
        for (int nt = 0; nt < 8; nt++) {
            int col = wc * 64 + nt * 8 + qc;
            #pragma unroll
            for (int h = 0; h < 2; h++) {
                int row = wr * 64 + mt * 16 + h * 8 + qr;
                size_t o = obase + (size_t)row * EE + col;
                float2 xr = *(const float2*)(x + o);
                float2 r;
                r.x = acc[mt][nt][h*2 + 0] + xr.x;
                r.y = acc[mt][nt][h*2 + 1] + xr.y;
                *(float2*)(out + o) = r;
            }
        }
    }
}

// ============================================================
extern "C" void kernel_launch(void* const* d_in, const int* in_sizes, int n_in,
                              void* d_out, int out_size) {
    const float* x  = (const float*)d_in[0];   // [B, T, E] fp32
    const float* dp = (const float*)d_in[1];   // [CS, L] fp32
    float* out = (float*)d_out;

    const int SC_SMEM  = 4 * 16384 + 1024 + 64;
    const int OUT_SMEM = 96 * 1024;
    cudaFuncSetAttribute(score_hmma_k, cudaFuncAttributeMaxDynamicSharedMemorySize, SC_SMEM);
    cudaFuncSetAttribute(out_hmma_k,   cudaFuncAttributeMaxDynamicSharedMemorySize, OUT_SMEM);

    normalize_k<<<(BB * TT) / 8, 256>>>(x);
    score_hmma_k<<<dim3(NCH, NCH, BB), 256, SC_SMEM>>>();
    topk_warp_k<<<dim3(NCH, BB), 32>>>();
    out_hmma_k<<<dim3(NCH, BB), 256, OUT_SMEM>>>(x, dp, out);
}